// round 14
// baseline (speedup 1.0000x reference)
#include <cuda_runtime.h>
#include <stdint.h>

// ---------------------------------------------------------------------------
// octree_level matching the reference's ACTUAL semantics (JAX x64 disabled:
// _key overflows int32; wrapped key = ((x&255)<<24)|(y<<12)|z, signed order).
//   - parent identity collapses px -> sx = px & 255
//   - signed sort == lexicographic (sx^128, py, pz), negative half first
//   - rows with key<0 (sx>=128) are invalid: coords (-1,-1,-1), occ 0
//   - child (i,j,k) of valid parent (sx,py,pz) occupied <=> exists leaf with
//     (x&255, y, z) == (2sx+i, 2py+j, 2pz+k)
//
// parent bitmap: 2^26 cells, idx = (sp<<18)|(py<<9)|pz, sp=(px&255)^128 (8MB)
//   chunk order (256 words) == reference row order: invalid chunks [0,4096),
//   valid chunks [4096,8192).
// leaf2 probe table (child-grouped): bit = (cell<<3)|m (32 MB),
//   cell = (((x&255)>>1)<<18)|((y>>1)<<9)|(z>>1), m = 4(x&1)+2(y&1)+(z&1)
//   -> a parent's 8-child occupancy is ONE byte of one word.
//
// Single-pass k_main (decoupled lookback over 8192 chunks): popcount own
// chunk -> publish aggregate -> warp-parallel lookback for global row prefix
// -> write rows (invalid chunks: flat constant fills; valid chunks: shared
// compaction + coalesced probe/emit). k_pad fills [np, n) afterwards.
//
// kernel_launch adapts to out_size (never writes beyond it):
//   out_size >= 11n : planar [parent_C float (3n) | occupancy float (8n)]
//   out_size ==  8n : occupancy only (float)
//   else            : parent_C only (int32)
// ---------------------------------------------------------------------------

#define LEAF2_WORDS (1u << 23)  // 2^28 bits -> 32 MB
#define PAR_WORDS   (1u << 21)  // 2^26 bits ->  8 MB
#define TPB         256
#define CWORDS      256                     // words per chunk
#define NCH         (PAR_WORDS / CWORDS)    // 8192 chunks
#define VCH         (NCH / 2)               // first valid chunk
#define CAP         2560                    // shared compaction capacity
#define FLAG_A      (1u << 30)
#define FLAG_P      (1u << 31)
#define VAL_MASK    0x00FFFFFFu

__device__ unsigned int g_leaf2[LEAF2_WORDS];
__device__ unsigned int g_par_bits[PAR_WORDS];
__device__ unsigned int g_state[NCH];   // lookback: flag | inclusive/aggregate
__device__ unsigned int g_np;           // total real rows

__device__ __forceinline__ int clamp1023(float v) {
    int x = (int)floorf(v);
    x = x < 0 ? 0 : x;
    return x > 1023 ? 1023 : x;
}

// --- scatter: parent bitmap only -------------------------------------------
__global__ void k_scatter_par(const float* __restrict__ leaf, int n) {
    int i = blockIdx.x * blockDim.x + threadIdx.x;
    if (i >= n) return;
    int x = clamp1023(leaf[3 * i + 0]);
    int y = clamp1023(leaf[3 * i + 1]);
    int z = clamp1023(leaf[3 * i + 2]);
    unsigned sp = (((unsigned)(x >> 1)) & 255u) ^ 128u;
    unsigned pidx = (sp << 18) | ((unsigned)(y >> 1) << 9) | (unsigned)(z >> 1);
    atomicOr(&g_par_bits[pidx >> 5], 1u << (pidx & 31));
}

// --- scatter: parent bitmap + child-grouped probe table --------------------
__global__ void k_scatter_full(const float* __restrict__ leaf, int n) {
    int i = blockIdx.x * blockDim.x + threadIdx.x;
    if (i >= n) return;
    int x = clamp1023(leaf[3 * i + 0]);
    int y = clamp1023(leaf[3 * i + 1]);
    int z = clamp1023(leaf[3 * i + 2]);
    unsigned sxp = ((unsigned)(x & 255)) >> 1;
    unsigned cell = (sxp << 18) | ((unsigned)(y >> 1) << 9) | (unsigned)(z >> 1);
    unsigned m = (((unsigned)x & 1u) << 2) | (((unsigned)y & 1u) << 1) | ((unsigned)z & 1u);
    atomicOr(&g_leaf2[cell >> 2], 1u << (((cell & 3u) << 3) | m));
    unsigned sp = (((unsigned)(x >> 1)) & 255u) ^ 128u;
    unsigned pidx = (sp << 18) | ((unsigned)(y >> 1) << 9) | (unsigned)(z >> 1);
    atomicOr(&g_par_bits[pidx >> 5], 1u << (pidx & 31));
}

// --- flat constant fill helpers (coalesced scalar stores) ------------------
__device__ __forceinline__ void fill_f(float* p, unsigned long long beg,
                                       unsigned long long end, float v, unsigned t) {
    for (unsigned long long i = beg + t; i < end; i += TPB) p[i] = v;
}
__device__ __forceinline__ void fill_i(int* p, unsigned long long beg,
                                       unsigned long long end, int v, unsigned t) {
    for (unsigned long long i = beg + t; i < end; i += TPB) p[i] = v;
}

// ---------------------------------------------------------------------------
// Single-pass scan + emit. Grid = NCH blocks, one 256-word chunk each.
// MODE 0: int32 coords; MODE 1: float coords + occ; MODE 2: occ only.
// ---------------------------------------------------------------------------
template <int MODE>
__global__ void k_main(void* __restrict__ out_raw, int n) {
    __shared__ unsigned int buf[CAP];
    __shared__ unsigned int warp_sc[TPB / 32];
    __shared__ unsigned int sh_prefix;

    int*   out_i   = (int*)out_raw;
    float* out_f   = (float*)out_raw;
    float* out_occ = (MODE == 1) ? out_f + 3ull * (unsigned long long)n : out_f;
    unsigned t = threadIdx.x;
    unsigned lane = t & 31, wrp = t >> 5;
    unsigned c = blockIdx.x;

    // --- phase 1: popcount + block scan ---
    unsigned w = c * CWORDS + t;
    unsigned bits = g_par_bits[w];
    unsigned p = __popc(bits);

    unsigned incl = p;
#pragma unroll
    for (int o = 1; o < 32; o <<= 1) {
        unsigned x = __shfl_up_sync(0xffffffffu, incl, o);
        if (lane >= (unsigned)o) incl += x;
    }
    if (lane == 31) warp_sc[wrp] = incl;
    __syncthreads();

    unsigned mrows = 0, warp_off = 0;
#pragma unroll
    for (unsigned ww = 0; ww < TPB / 32; ww++) {
        unsigned v = warp_sc[ww];
        if (ww < wrp) warp_off += v;
        mrows += v;
    }
    unsigned pos = warp_off + incl - p;       // block-local rank

    // --- phase 2: publish aggregate, warp-parallel lookback ---
    if (t == 0)
        *(volatile unsigned*)&g_state[c] = FLAG_A | (mrows & VAL_MASK);
    if (t < 32) {
        unsigned run = 0;
        int j = (int)c - 1;
        while (j >= 0) {
            int idx = j - (int)t;
            unsigned s;
            do {
                s = (idx >= 0) ? *(volatile unsigned*)&g_state[idx] : FLAG_P;
            } while (__any_sync(0xffffffffu, s == 0u));
            unsigned pm = __ballot_sync(0xffffffffu, (s & FLAG_P) != 0u);
            unsigned v = s & VAL_MASK;
            unsigned contrib;
            if (pm) {
                int fp = __ffs(pm) - 1;       // nearest P (largest idx)
                contrib = (t <= (unsigned)fp) ? v : 0u;
            } else {
                contrib = v;
            }
#pragma unroll
            for (int o = 16; o; o >>= 1) contrib += __shfl_down_sync(0xffffffffu, contrib, o);
            run += __shfl_sync(0xffffffffu, contrib, 0);
            if (pm) break;
            j -= 32;
        }
        if (t == 0) {
            sh_prefix = run;
            *(volatile unsigned*)&g_state[c] = FLAG_P | ((run + mrows) & VAL_MASK);
            if (c == NCH - 1) g_np = run + mrows;
        }
    }
    __syncthreads();
    unsigned r0 = sh_prefix;

    // --- phase 3: write rows ---
    if (c < VCH) {
        // invalid half: constant rows, flat coalesced fills
        if (mrows == 0) return;
        unsigned long long a = r0, b = r0 + mrows;
        if (MODE == 0) {
            fill_i(out_i, 3ull * a, 3ull * b, -1, t);
        } else if (MODE == 1) {
            fill_f(out_f, 3ull * a, 3ull * b, -1.0f, t);
            fill_f(out_occ, 8ull * a, 8ull * b, 0.0f, t);
        } else {
            fill_f(out_occ, 8ull * a, 8ull * b, 0.0f, t);
        }
        return;
    }

    // valid half
    unsigned cell_base = (w << 5) - (1u << 25);   // sp>=128 -> sx<128
    if (mrows <= CAP) {
        // compact to shared, then coalesced row-per-thread writes
        unsigned bb = bits, q = pos;
        while (bb) {
            int b = __ffs(bb) - 1;
            bb &= bb - 1;
            buf[q++] = cell_base | (unsigned)b;
        }
        __syncthreads();
        for (unsigned i = t; i < mrows; i += TPB) {
            unsigned cell = buf[i];
            unsigned r = r0 + i;
            unsigned sx = cell >> 18;
            unsigned py = (cell >> 9) & 511u;
            unsigned pz = cell & 511u;
            if (MODE == 0) {
                unsigned long long r3 = 3ull * r;
                out_i[r3 + 0] = (int)sx;
                out_i[r3 + 1] = (int)py;
                out_i[r3 + 2] = (int)pz;
            } else if (MODE == 1) {
                unsigned long long r3 = 3ull * r;
                out_f[r3 + 0] = (float)sx;
                out_f[r3 + 1] = (float)py;
                out_f[r3 + 2] = (float)pz;
            }
            if (MODE != 0) {
                unsigned lw = g_leaf2[cell >> 2];
                unsigned byt = (lw >> ((cell & 3u) << 3)) & 255u;
                float4 o0 = make_float4((float)(byt & 1u), (float)((byt >> 1) & 1u),
                                        (float)((byt >> 2) & 1u), (float)((byt >> 3) & 1u));
                float4 o1 = make_float4((float)((byt >> 4) & 1u), (float)((byt >> 5) & 1u),
                                        (float)((byt >> 6) & 1u), (float)((byt >> 7) & 1u));
                float4* dst = (float4*)(out_occ + 8ull * r);
                dst[0] = o0;
                dst[1] = o1;
            }
        }
    } else {
        // fallback (never on sane data): direct per-thread emission
        unsigned r = r0 + pos;
        unsigned bb = bits;
        while (bb) {
            int b = __ffs(bb) - 1;
            bb &= bb - 1;
            unsigned cell = cell_base | (unsigned)b;
            unsigned sx = cell >> 18;
            unsigned py = (cell >> 9) & 511u;
            unsigned pz = cell & 511u;
            if (MODE == 0) {
                unsigned long long r3 = 3ull * r;
                out_i[r3 + 0] = (int)sx; out_i[r3 + 1] = (int)py; out_i[r3 + 2] = (int)pz;
            } else if (MODE == 1) {
                unsigned long long r3 = 3ull * r;
                out_f[r3 + 0] = (float)sx; out_f[r3 + 1] = (float)py; out_f[r3 + 2] = (float)pz;
            }
            if (MODE != 0) {
                unsigned lw = g_leaf2[cell >> 2];
                unsigned byt = (lw >> ((cell & 3u) << 3)) & 255u;
#pragma unroll
                for (int k = 0; k < 8; k++)
                    out_occ[8ull * r + (unsigned)k] = (float)((byt >> k) & 1u);
            }
            r++;
        }
    }
}

// --- pad rows [np, n): coords -1, occ 0 ------------------------------------
template <int MODE>
__global__ void k_pad(void* __restrict__ out_raw, int n) {
    unsigned np = g_np;
    unsigned i = blockIdx.x * blockDim.x + threadIdx.x;
    if (i >= (unsigned)n || i < np) return;
    int*   out_i = (int*)out_raw;
    float* out_f = (float*)out_raw;
    if (MODE == 0) {
        unsigned long long i3 = 3ull * i;
        out_i[i3 + 0] = -1; out_i[i3 + 1] = -1; out_i[i3 + 2] = -1;
    } else if (MODE == 1) {
        unsigned long long i3 = 3ull * i;
        out_f[i3 + 0] = -1.0f; out_f[i3 + 1] = -1.0f; out_f[i3 + 2] = -1.0f;
        float4* oo = (float4*)(out_f + 3ull * (unsigned long long)n + 8ull * i);
        float4 z = make_float4(0.f, 0.f, 0.f, 0.f);
        oo[0] = z; oo[1] = z;
    } else {
        float4* oo = (float4*)(out_f + 8ull * i);
        float4 z = make_float4(0.f, 0.f, 0.f, 0.f);
        oo[0] = z; oo[1] = z;
    }
}

extern "C" void kernel_launch(void* const* d_in, const int* in_sizes, int n_in,
                              void* d_out, int out_size) {
    const float* leaf = (const float*)d_in[0];
    int n = in_sizes[0] / 3;
    int grid_n = (n + TPB - 1) / TPB;

    void* pp = nullptr;
    void* ps = nullptr;
    cudaGetSymbolAddress(&pp, g_par_bits);
    cudaGetSymbolAddress(&ps, g_state);
    cudaMemsetAsync(pp, 0, (size_t)PAR_WORDS * sizeof(unsigned int));
    cudaMemsetAsync(ps, 0, (size_t)NCH * sizeof(unsigned int));

    bool need_occ = (out_size >= 11 * n) || (out_size == 8 * n);
    if (need_occ) {
        void* pl = nullptr;
        cudaGetSymbolAddress(&pl, g_leaf2);
        cudaMemsetAsync(pl, 0, (size_t)LEAF2_WORDS * sizeof(unsigned int));
        k_scatter_full<<<grid_n, TPB>>>(leaf, n);
    } else {
        k_scatter_par<<<grid_n, TPB>>>(leaf, n);
    }

    if (out_size >= 11 * n) {
        k_main<1><<<NCH, TPB>>>(d_out, n);
        k_pad<1><<<grid_n, TPB>>>(d_out, n);
    } else if (out_size == 8 * n) {
        k_main<2><<<NCH, TPB>>>(d_out, n);
        k_pad<2><<<grid_n, TPB>>>(d_out, n);
    } else {
        k_main<0><<<NCH, TPB>>>(d_out, n);
        k_pad<0><<<grid_n, TPB>>>(d_out, n);
    }
}

// round 15
// speedup vs baseline: 2.0422x; 2.0422x over previous
#include <cuda_runtime.h>
#include <stdint.h>

// ---------------------------------------------------------------------------
// octree_level matching the reference's ACTUAL semantics (JAX x64 disabled:
// _key overflows int32; wrapped key = ((x&255)<<24)|(y<<12)|z, signed order).
//   - parent identity collapses px -> sx = px & 255
//   - signed sort == lexicographic (sx^128, py, pz), negative half first
//   - rows with key<0 (sx>=128) are invalid: coords (-1,-1,-1), occ 0
//   - child (i,j,k) of valid parent (sx,py,pz) occupied <=> exists leaf with
//     (x&255, y, z) == (2sx+i, 2py+j, 2pz+k)
//
// parent bitmap: 2^26 cells, idx = (sp<<18)|(py<<9)|pz, sp=(px&255)^128 (8MB)
// leaf2 probe table (child-grouped): bit = (cell<<3)|m (32 MB),
//   cell = (((x&255)>>1)<<18)|((y>>1)<<9)|(z>>1), m = 4(x&1)+2(y&1)+(z&1)
//   -> a parent's 8-child occupancy is ONE byte of one word.
//
// Pipeline: memset -> scatter (4 leaves/thread, float4 loads, 8 REDG ILP) ->
// per-chunk popcount -> single-block scan -> fused emit+fill (each of 4096
// blocks emits its valid chunk coalesced via shared compaction, then
// grid-strides a slice of the constant regions [0,invN) and [np,n)).
//
// kernel_launch adapts to out_size (never writes beyond it):
//   out_size >= 11n : planar [parent_C float (3n) | occupancy float (8n)]
//   out_size ==  8n : occupancy only (float)
//   else            : parent_C only (int32)
// ---------------------------------------------------------------------------

#define LEAF2_WORDS (1u << 23)  // 2^28 bits -> 32 MB
#define PAR_WORDS   (1u << 21)  // 2^26 bits ->  8 MB
#define TPB         256
#define CWORDS      256                     // words per chunk
#define NCH         (PAR_WORDS / CWORDS)    // 8192 chunks
#define VCH         (NCH / 2)               // 4096 valid-half chunks
#define SCAN_T      1024                    // k_scan threads (8 vals each)
#define CAP         2560                    // shared compaction capacity (10KB)

__device__ unsigned int g_leaf2[LEAF2_WORDS];
__device__ unsigned int g_par_bits[PAR_WORDS];
__device__ unsigned int g_chunk_sums[NCH];
__device__ unsigned int g_chunk_excl[NCH + 1];   // [NCH] = np, [VCH] = invN

__device__ __forceinline__ int clamp1023(float v) {
    int x = (int)floorf(v);
    x = x < 0 ? 0 : x;
    return x > 1023 ? 1023 : x;
}

__device__ __forceinline__ void scat_one_full(int x, int y, int z) {
    unsigned sxp = ((unsigned)(x & 255)) >> 1;
    unsigned cell = (sxp << 18) | ((unsigned)(y >> 1) << 9) | (unsigned)(z >> 1);
    unsigned m = (((unsigned)x & 1u) << 2) | (((unsigned)y & 1u) << 1) | ((unsigned)z & 1u);
    atomicOr(&g_leaf2[cell >> 2], 1u << (((cell & 3u) << 3) | m));
    unsigned sp = (((unsigned)(x >> 1)) & 255u) ^ 128u;
    unsigned pidx = (sp << 18) | ((unsigned)(y >> 1) << 9) | (unsigned)(z >> 1);
    atomicOr(&g_par_bits[pidx >> 5], 1u << (pidx & 31));
}

__device__ __forceinline__ void scat_one_par(int x, int y, int z) {
    unsigned sp = (((unsigned)(x >> 1)) & 255u) ^ 128u;
    unsigned pidx = (sp << 18) | ((unsigned)(y >> 1) << 9) | (unsigned)(z >> 1);
    atomicOr(&g_par_bits[pidx >> 5], 1u << (pidx & 31));
}

// --- scatter, 4 leaves per thread via 3x float4 ----------------------------
template <int FULL>
__global__ void k_scatter4(const float* __restrict__ leaf, int n) {
    int q = blockIdx.x * blockDim.x + threadIdx.x;   // quad index
    int base = q * 4;
    if (base >= n) return;
    if (base + 4 <= n) {
        const float4* lf4 = (const float4*)leaf;
        float4 a = lf4[3 * q + 0];
        float4 b = lf4[3 * q + 1];
        float4 c = lf4[3 * q + 2];
        int x0 = clamp1023(a.x), y0 = clamp1023(a.y), z0 = clamp1023(a.z);
        int x1 = clamp1023(a.w), y1 = clamp1023(b.x), z1 = clamp1023(b.y);
        int x2 = clamp1023(b.z), y2 = clamp1023(b.w), z2 = clamp1023(c.x);
        int x3 = clamp1023(c.y), y3 = clamp1023(c.z), z3 = clamp1023(c.w);
        if (FULL) {
            scat_one_full(x0, y0, z0); scat_one_full(x1, y1, z1);
            scat_one_full(x2, y2, z2); scat_one_full(x3, y3, z3);
        } else {
            scat_one_par(x0, y0, z0); scat_one_par(x1, y1, z1);
            scat_one_par(x2, y2, z2); scat_one_par(x3, y3, z3);
        }
    } else {
        for (int i = base; i < n; i++) {
            int x = clamp1023(leaf[3 * i + 0]);
            int y = clamp1023(leaf[3 * i + 1]);
            int z = clamp1023(leaf[3 * i + 2]);
            if (FULL) scat_one_full(x, y, z);
            else      scat_one_par(x, y, z);
        }
    }
}

// --- per-chunk popcount: 256 threads, 1 word each --------------------------
__global__ void k_count() {
    __shared__ unsigned int warp_sums[TPB / 32];
    unsigned t = threadIdx.x;
    unsigned s = __popc(g_par_bits[blockIdx.x * CWORDS + t]);
#pragma unroll
    for (int o = 16; o; o >>= 1) s += __shfl_down_sync(0xffffffffu, s, o);
    if ((t & 31) == 0) warp_sums[t >> 5] = s;
    __syncthreads();
    if (t == 0) {
        unsigned tot = 0;
#pragma unroll
        for (int w = 0; w < TPB / 32; w++) tot += warp_sums[w];
        g_chunk_sums[blockIdx.x] = tot;
    }
}

// --- exclusive scan of 8192 chunk sums (one block, 1024 thr, 8 vals each) --
__global__ void k_scan() {
    __shared__ unsigned int sh[SCAN_T];
    unsigned t = threadIdx.x;
    unsigned v[8], s = 0;
#pragma unroll
    for (int j = 0; j < 8; j++) { v[j] = g_chunk_sums[8 * t + j]; s += v[j]; }
    sh[t] = s;
    __syncthreads();
    for (int o = 1; o < SCAN_T; o <<= 1) {
        unsigned x = (t >= (unsigned)o) ? sh[t - o] : 0u;
        __syncthreads();
        sh[t] += x;
        __syncthreads();
    }
    unsigned base = sh[t] - s;
#pragma unroll
    for (int j = 0; j < 8; j++) { g_chunk_excl[8 * t + j] = base; base += v[j]; }
    if (t == SCAN_T - 1) g_chunk_excl[NCH] = sh[t];
}

// ---------------------------------------------------------------------------
// Fused emit + fill: grid = VCH blocks. Each block:
//  (a) compacts set bits of valid chunk VCH+bid into shared (CAP-bounded;
//      direct-emit fallback keeps correctness for any data), writes rows
//      coalesced, row-per-thread;
//  (b) grid-strides its slice of the constant regions [0,invN) and [np,n).
// MODE 0: int32 coords; MODE 1: float coords + occ; MODE 2: occ only.
// ---------------------------------------------------------------------------
template <int MODE>
__global__ void k_emit_fill(void* __restrict__ out_raw, int n) {
    __shared__ unsigned int buf[CAP];
    __shared__ unsigned int warp_sc[TPB / 32];

    int*   out_i   = (int*)out_raw;
    float* out_f   = (float*)out_raw;
    float* out_occ = (MODE == 1) ? out_f + 3ull * (unsigned long long)n : out_f;
    unsigned t = threadIdx.x;
    unsigned lane = t & 31, wrp = t >> 5;

    // ---------------- emit: phase 1, rank within chunk ----------------
    unsigned chunk = VCH + blockIdx.x;
    unsigned w = chunk * CWORDS + t;
    unsigned bits = g_par_bits[w];
    unsigned p = __popc(bits);

    unsigned incl = p;
#pragma unroll
    for (int o = 1; o < 32; o <<= 1) {
        unsigned x = __shfl_up_sync(0xffffffffu, incl, o);
        if (lane >= (unsigned)o) incl += x;
    }
    if (lane == 31) warp_sc[wrp] = incl;
    __syncthreads();
    unsigned mrows = 0, warp_off = 0;
#pragma unroll
    for (unsigned ww = 0; ww < TPB / 32; ww++) {
        unsigned v = warp_sc[ww];
        if (ww < wrp) warp_off += v;
        mrows += v;
    }
    unsigned pos = warp_off + incl - p;           // block-local rank
    unsigned r0 = g_chunk_excl[chunk];
    unsigned cell_base = (w << 5) - (1u << 25);   // valid half: sp>=128 -> sx<128

    if (mrows <= CAP) {
        // phase 2a: compact to shared, then coalesced row writes
        unsigned bb = bits, q = pos;
        while (bb) {
            int b = __ffs(bb) - 1;
            bb &= bb - 1;
            buf[q++] = cell_base | (unsigned)b;
        }
        __syncthreads();
        for (unsigned i = t; i < mrows; i += TPB) {
            unsigned cell = buf[i];
            unsigned r = r0 + i;
            unsigned sx = cell >> 18;
            unsigned py = (cell >> 9) & 511u;
            unsigned pz = cell & 511u;
            if (MODE == 0) {
                unsigned long long r3 = 3ull * r;
                out_i[r3 + 0] = (int)sx;
                out_i[r3 + 1] = (int)py;
                out_i[r3 + 2] = (int)pz;
            } else if (MODE == 1) {
                unsigned long long r3 = 3ull * r;
                out_f[r3 + 0] = (float)sx;
                out_f[r3 + 1] = (float)py;
                out_f[r3 + 2] = (float)pz;
            }
            if (MODE != 0) {
                unsigned lw = g_leaf2[cell >> 2];
                unsigned byt = (lw >> ((cell & 3u) << 3)) & 255u;
                float4 o0 = make_float4((float)(byt & 1u), (float)((byt >> 1) & 1u),
                                        (float)((byt >> 2) & 1u), (float)((byt >> 3) & 1u));
                float4 o1 = make_float4((float)((byt >> 4) & 1u), (float)((byt >> 5) & 1u),
                                        (float)((byt >> 6) & 1u), (float)((byt >> 7) & 1u));
                float4* dst = (float4*)(out_occ + 8ull * r);
                dst[0] = o0;
                dst[1] = o1;
            }
        }
    } else {
        // phase 2b fallback: direct per-thread emission (correct for any data)
        unsigned r = r0 + pos;
        unsigned bb = bits;
        while (bb) {
            int b = __ffs(bb) - 1;
            bb &= bb - 1;
            unsigned cell = cell_base | (unsigned)b;
            unsigned sx = cell >> 18;
            unsigned py = (cell >> 9) & 511u;
            unsigned pz = cell & 511u;
            if (MODE == 0) {
                unsigned long long r3 = 3ull * r;
                out_i[r3 + 0] = (int)sx; out_i[r3 + 1] = (int)py; out_i[r3 + 2] = (int)pz;
            } else if (MODE == 1) {
                unsigned long long r3 = 3ull * r;
                out_f[r3 + 0] = (float)sx; out_f[r3 + 1] = (float)py; out_f[r3 + 2] = (float)pz;
            }
            if (MODE != 0) {
                unsigned lw = g_leaf2[cell >> 2];
                unsigned byt = (lw >> ((cell & 3u) << 3)) & 255u;
#pragma unroll
                for (int k = 0; k < 8; k++)
                    out_occ[8ull * r + (unsigned)k] = (float)((byt >> k) & 1u);
            }
            r++;
        }
        __syncthreads();
    }

    // ---------------- fill: constant regions ----------------
    unsigned invN = g_chunk_excl[VCH];            // rows of negative-key half
    unsigned np   = g_chunk_excl[NCH];            // total real rows
    float4 z4 = make_float4(0.f, 0.f, 0.f, 0.f);
    const unsigned stride = VCH * TPB;

    for (unsigned i = blockIdx.x * TPB + t; i < invN; i += stride) {
        if (MODE == 0) {
            unsigned long long i3 = 3ull * i;
            out_i[i3 + 0] = -1; out_i[i3 + 1] = -1; out_i[i3 + 2] = -1;
        } else if (MODE == 1) {
            unsigned long long i3 = 3ull * i;
            out_f[i3 + 0] = -1.0f; out_f[i3 + 1] = -1.0f; out_f[i3 + 2] = -1.0f;
            float4* oo = (float4*)(out_occ + 8ull * i);
            oo[0] = z4; oo[1] = z4;
        } else {
            float4* oo = (float4*)(out_occ + 8ull * i);
            oo[0] = z4; oo[1] = z4;
        }
    }
    for (unsigned i = np + blockIdx.x * TPB + t; i < (unsigned)n; i += stride) {
        if (MODE == 0) {
            unsigned long long i3 = 3ull * i;
            out_i[i3 + 0] = -1; out_i[i3 + 1] = -1; out_i[i3 + 2] = -1;
        } else if (MODE == 1) {
            unsigned long long i3 = 3ull * i;
            out_f[i3 + 0] = -1.0f; out_f[i3 + 1] = -1.0f; out_f[i3 + 2] = -1.0f;
            float4* oo = (float4*)(out_occ + 8ull * i);
            oo[0] = z4; oo[1] = z4;
        } else {
            float4* oo = (float4*)(out_occ + 8ull * i);
            oo[0] = z4; oo[1] = z4;
        }
    }
}

extern "C" void kernel_launch(void* const* d_in, const int* in_sizes, int n_in,
                              void* d_out, int out_size) {
    const float* leaf = (const float*)d_in[0];
    int n = in_sizes[0] / 3;
    int nq = (n + 3) / 4;
    int grid_q = (nq + TPB - 1) / TPB;

    void* pp = nullptr;
    cudaGetSymbolAddress(&pp, g_par_bits);
    cudaMemsetAsync(pp, 0, (size_t)PAR_WORDS * sizeof(unsigned int));

    bool need_occ = (out_size >= 11 * n) || (out_size == 8 * n);
    if (need_occ) {
        void* pl = nullptr;
        cudaGetSymbolAddress(&pl, g_leaf2);
        cudaMemsetAsync(pl, 0, (size_t)LEAF2_WORDS * sizeof(unsigned int));
        k_scatter4<1><<<grid_q, TPB>>>(leaf, n);
    } else {
        k_scatter4<0><<<grid_q, TPB>>>(leaf, n);
    }

    k_count<<<NCH, TPB>>>();
    k_scan<<<1, SCAN_T>>>();

    if (out_size >= 11 * n) {
        k_emit_fill<1><<<VCH, TPB>>>(d_out, n);
    } else if (out_size == 8 * n) {
        k_emit_fill<2><<<VCH, TPB>>>(d_out, n);
    } else {
        k_emit_fill<0><<<VCH, TPB>>>(d_out, n);
    }
}